// round 1
// baseline (speedup 1.0000x reference)
#include <cuda_runtime.h>

#define N_MODES   16
#define N_PAIR    120
#define N_LAYERS  6
#define LIN_P     528           // 4*120 + 3*16
#define OUT_COLS  10
#define TPB       256

// ---------------------------------------------------------------------------
// Device-global scratch (allocation-free per harness rules)
// ---------------------------------------------------------------------------
__device__ float g_S[12][32][32];            // real symplectic mats: [2*l + which][row][col]
__device__ float g_W[N_LAYERS][32][32];      // composed weights, TRANSPOSED: g_W[l][in][out]
__device__ float g_d[N_LAYERS][32];          // displacements

// ---------------------------------------------------------------------------
// f32x2 packed-FMA helpers (Blackwell FFMA2)
// ---------------------------------------------------------------------------
__device__ __forceinline__ unsigned long long ffma2(unsigned long long a,
                                                    unsigned long long b,
                                                    unsigned long long c) {
    unsigned long long d;
    asm("fma.rn.f32x2 %0, %1, %2, %3;" : "=l"(d) : "l"(a), "l"(b), "l"(c));
    return d;
}
__device__ __forceinline__ unsigned long long dup_f32(float x) {
    unsigned long long d;
    unsigned int u = __float_as_uint(x);
    asm("mov.b64 %0, {%1, %1};" : "=l"(d) : "r"(u));
    return d;
}
__device__ __forceinline__ unsigned long long pack2(float x, float y) {
    unsigned long long d;
    asm("mov.b64 %0, {%1, %2};" : "=l"(d)
        : "r"(__float_as_uint(x)), "r"(__float_as_uint(y)));
    return d;
}
__device__ __forceinline__ void unpack2(unsigned long long a, float& x, float& y) {
    unsigned int lo, hi;
    asm("mov.b64 {%0, %1}, %2;" : "=r"(lo), "=r"(hi) : "l"(a));
    x = __uint_as_float(lo);
    y = __uint_as_float(hi);
}

// ---------------------------------------------------------------------------
// Setup kernel: build per-layer 32x32 affine maps from linear_params.
// One block, 1024 threads.
//   Phase 1: 12 groups x 16 threads; group g = 2*layer + which builds U (16x16
//            complex) column-wise in registers via the 120-step BS scan, then
//            expands to the real 32x32 symplectic in g_S[g].
//   Phase 2: all 1024 threads compose W[o][i] = sum_k S2[o][k]*scale[k]*S1[k][i]
//            (stored transposed as g_W[l][i][o]).
// ---------------------------------------------------------------------------
__global__ void setup_kernel(const float* __restrict__ lin) {
    int tid = threadIdx.x;
    __shared__ float s_scale[N_LAYERS][32];

    if (tid < 192) {
        // ---- interferometer scan ----
        int g   = tid >> 4;          // 0..11
        int col = tid & 15;
        int l   = g >> 1;
        int w   = g & 1;
        const float* lp = lin + l * LIN_P;
        const float* th = lp + (w ? 256 : 0);
        const float* ph = lp + (w ? 376 : 120);

        float ur[16], ui[16];
        #pragma unroll
        for (int m = 0; m < 16; ++m) { ur[m] = (m == col) ? 1.f : 0.f; ui[m] = 0.f; }

        int k = 0;
        #pragma unroll
        for (int i = 0; i < 16; ++i) {
            #pragma unroll
            for (int j = i + 1; j < 16; ++j) {
                float t = th[k], p = ph[k];
                float s, c, sp, cp;
                sincosf(t, &s, &c);
                sincosf(p, &sp, &cp);
                float br = cp * s, bi = sp * s;      // e*s = (br, bi)
                float air = ur[i], aii = ui[i];
                float ajr = ur[j], aji = ui[j];
                // U[i] = c*ri - conj(e)*s*rj ; conj(e)*s = (br, -bi)
                ur[i] = c * air - (br * ajr + bi * aji);
                ui[i] = c * aii - (br * aji - bi * ajr);
                // U[j] = e*s*ri + c*rj
                ur[j] = (br * air - bi * aii) + c * ajr;
                ui[j] = (br * aii + bi * air) + c * aji;
                ++k;
            }
        }
        // expand to real symplectic: [[Re, -Im], [Im, Re]]
        #pragma unroll
        for (int m = 0; m < 16; ++m) {
            g_S[g][m][col]           =  ur[m];
            g_S[g][m][col + 16]      = -ui[m];
            g_S[g][m + 16][col]      =  ui[m];
            g_S[g][m + 16][col + 16] =  ur[m];
        }
    }

    if (tid < 192) {
        // ---- squeezing scales + displacement ----
        int l = tid >> 5, kk = tid & 31;
        const float* lp = lin + l * LIN_P;
        float r = lp[240 + (kk & 15)];
        s_scale[l][kk] = expf(kk < 16 ? -r : r);
        g_d[l][kk] = lp[496 + kk];
    }
    __syncthreads();

    // ---- compose W ----
    {
        int i = tid >> 5, o = tid & 31;     // i = input idx, o = output idx
        #pragma unroll 1
        for (int l = 0; l < N_LAYERS; ++l) {
            float acc = 0.f;
            #pragma unroll
            for (int k = 0; k < 32; ++k)
                acc += g_S[2 * l + 1][o][k] * s_scale[l][k] * g_S[2 * l][k][i];
            g_W[l][i][o] = acc;
        }
    }
}

// ---------------------------------------------------------------------------
// Affine layer: v <- W v + d, outputs packed two-per-f32x2 (pairs 2k, 2k+1).
// sWl points at 32x32 floats laid out [in][out]; thread-uniform -> LDS broadcast.
// ---------------------------------------------------------------------------
__device__ __forceinline__ void linear_layer(float v[32],
                                             const float* __restrict__ sWl,
                                             const float* __restrict__ sdl) {
    unsigned long long acc[16];
    #pragma unroll
    for (int k = 0; k < 16; ++k) acc[k] = pack2(sdl[2 * k], sdl[2 * k + 1]);

    #pragma unroll
    for (int i = 0; i < 32; ++i) {
        unsigned long long vd = dup_f32(v[i]);
        const ulonglong2* wr = reinterpret_cast<const ulonglong2*>(sWl + i * 32);
        #pragma unroll
        for (int k = 0; k < 8; ++k) {
            ulonglong2 w2 = wr[k];                       // LDS.128: 4 weights = 2 pairs
            acc[2 * k]     = ffma2(vd, w2.x, acc[2 * k]);
            acc[2 * k + 1] = ffma2(vd, w2.y, acc[2 * k + 1]);
        }
    }
    #pragma unroll
    for (int k = 0; k < 16; ++k) unpack2(acc[k], v[2 * k], v[2 * k + 1]);
}

// ---------------------------------------------------------------------------
// Main kernel: one thread = one sample; state in registers; weights in SMEM.
// ---------------------------------------------------------------------------
__global__ void __launch_bounds__(TPB) qnet_main(
    const float* __restrict__ batch,
    const float* __restrict__ act_p,      // (5, 16)
    const float* __restrict__ last_act,   // (16,)
    float* __restrict__ out,
    int n_samples)
{
    __shared__ __align__(16) float sW[N_LAYERS][32][32];   // 24 KB
    __shared__ float sd[N_LAYERS][32];
    __shared__ float sk[N_LAYERS][16];

    int tid = threadIdx.x;
    {
        const float4* src = reinterpret_cast<const float4*>(g_W);
        float4* dst = reinterpret_cast<float4*>(&sW[0][0][0]);
        for (int idx = tid; idx < N_LAYERS * 32 * 32 / 4; idx += TPB) dst[idx] = src[idx];
        if (tid < N_LAYERS * 32) (&sd[0][0])[tid] = (&g_d[0][0])[tid];
        if (tid < 80)                      (&sk[0][0])[tid] = act_p[tid];
        else if (tid < 96)                 (&sk[0][0])[tid] = last_act[tid - 80];
    }
    __syncthreads();

    int sample = blockIdx.x * TPB + tid;
    if (sample >= n_samples) return;

    float v[32];
    {
        const float4* br = reinterpret_cast<const float4*>(batch + (size_t)sample * 16);
        float4 b0 = br[0], b1 = br[1], b2 = br[2], b3 = br[3];
        v[0] = b0.x;  v[1] = b0.y;  v[2] = b0.z;  v[3] = b0.w;
        v[4] = b1.x;  v[5] = b1.y;  v[6] = b1.z;  v[7] = b1.w;
        v[8] = b2.x;  v[9] = b2.y;  v[10] = b2.z; v[11] = b2.w;
        v[12] = b3.x; v[13] = b3.y; v[14] = b3.z; v[15] = b3.w;
        #pragma unroll
        for (int m = 16; m < 32; ++m) v[m] = 0.f;
    }

    // layers 0..4: linear + full-width Kerr activation
    #pragma unroll 1
    for (int l = 0; l < N_LAYERS - 1; ++l) {
        linear_layer(v, &sW[l][0][0], &sd[l][0]);
        const float* kp = &sk[l][0];
        #pragma unroll
        for (int m = 0; m < 16; ++m) {
            float x = v[m], p = v[m + 16];
            float ang = kp[m] * (x * x + p * p);
            float s, c;
            __sincosf(ang, &s, &c);
            v[m]      = fmaf(c, x,  s * p);
            v[m + 16] = fmaf(c, p, -s * x);
        }
    }

    // last linear + activation on first OUT_COLS modes only; emit x-part
    linear_layer(v, &sW[N_LAYERS - 1][0][0], &sd[N_LAYERS - 1][0]);
    float o10[OUT_COLS];
    #pragma unroll
    for (int m = 0; m < OUT_COLS; ++m) {
        float x = v[m], p = v[m + 16];
        float ang = sk[N_LAYERS - 1][m] * (x * x + p * p);
        float s, c;
        __sincosf(ang, &s, &c);
        o10[m] = fmaf(c, x, s * p);
    }

    // row byte offset = sample*40, 8B-aligned -> five STG.64
    float2* orow = reinterpret_cast<float2*>(out + (size_t)sample * OUT_COLS);
    #pragma unroll
    for (int m = 0; m < 5; ++m) orow[m] = make_float2(o10[2 * m], o10[2 * m + 1]);
}

// ---------------------------------------------------------------------------
extern "C" void kernel_launch(void* const* d_in, const int* in_sizes, int n_in,
                              void* d_out, int out_size) {
    const float* batch    = (const float*)d_in[0];   // (B, 16)
    const float* lin      = (const float*)d_in[1];   // (6, 528)
    const float* act_p    = (const float*)d_in[2];   // (5, 16)
    const float* last_act = (const float*)d_in[3];   // (16,)
    float* out = (float*)d_out;

    int n_samples = in_sizes[0] / N_MODES;
    int blocks = (n_samples + TPB - 1) / TPB;

    setup_kernel<<<1, 1024>>>(lin);
    qnet_main<<<blocks, TPB>>>(batch, act_p, last_act, out, n_samples);
}

// round 4
// speedup vs baseline: 1.4866x; 1.4866x over previous
#include <cuda_runtime.h>

#define N_MODES   16
#define N_LAYERS  6
#define LIN_P     528           // 4*120 + 3*16
#define OUT_COLS  10
#define TPB       128
#define SPT       2             // samples per thread

typedef unsigned long long ull;

// ---------------------------------------------------------------------------
// Device-global scratch (allocation-free per harness rules)
// ---------------------------------------------------------------------------
__device__ float g_S[12][32][32];            // real symplectic mats
__device__ float g_W[N_LAYERS][32][32];      // composed weights, TRANSPOSED: [l][in][out]
__device__ float g_Wc[32][20];               // last layer compact: [in][x0..x9,p0..p9]
__device__ float g_d[N_LAYERS][32];          // displacements
__device__ float g_dc[20];                   // last-layer displacement, compact

// ---------------------------------------------------------------------------
// f32x2 packed-FMA helpers (Blackwell FFMA2)
// ---------------------------------------------------------------------------
__device__ __forceinline__ ull ffma2(ull a, ull b, ull c) {
    ull d;
    asm("fma.rn.f32x2 %0, %1, %2, %3;" : "=l"(d) : "l"(a), "l"(b), "l"(c));
    return d;
}
__device__ __forceinline__ ull dup_f32(float x) {
    ull d;
    unsigned int u = __float_as_uint(x);
    asm("mov.b64 %0, {%1, %1};" : "=l"(d) : "r"(u));
    return d;
}
__device__ __forceinline__ ull pack2(float x, float y) {
    ull d;
    asm("mov.b64 %0, {%1, %2};" : "=l"(d)
        : "r"(__float_as_uint(x)), "r"(__float_as_uint(y)));
    return d;
}
__device__ __forceinline__ void unpack2(ull a, float& x, float& y) {
    unsigned int lo, hi;
    asm("mov.b64 {%0, %1}, %2;" : "=r"(lo), "=r"(hi) : "l"(a));
    x = __uint_as_float(lo);
    y = __uint_as_float(hi);
}

// ---------------------------------------------------------------------------
// Setup kernel: build per-layer 32x32 affine maps from linear_params.
// One block, 1024 threads. MUFU intrinsics: angles/squeezes are O(1e-3);
// accumulated weight error ~1e-5, negligible vs the 1e-3 test tolerance.
// ---------------------------------------------------------------------------
__global__ void setup_kernel(const float* __restrict__ lin) {
    int tid = threadIdx.x;
    __shared__ float s_scale[N_LAYERS][32];

    if (tid < 192) {
        // ---- interferometer scan: 12 groups x 16 threads, one column each ----
        int g   = tid >> 4;          // 0..11 = 2*layer + which
        int col = tid & 15;
        int l   = g >> 1;
        int w   = g & 1;
        const float* lp = lin + l * LIN_P;
        const float* th = lp + (w ? 256 : 0);
        const float* ph = lp + (w ? 376 : 120);

        float ur[16], ui[16];
        #pragma unroll
        for (int m = 0; m < 16; ++m) { ur[m] = (m == col) ? 1.f : 0.f; ui[m] = 0.f; }

        int k = 0;
        #pragma unroll
        for (int i = 0; i < 16; ++i) {
            #pragma unroll
            for (int j = i + 1; j < 16; ++j) {
                float t = th[k], p = ph[k];
                float s, c, sp, cp;
                __sincosf(t, &s, &c);
                __sincosf(p, &sp, &cp);
                float br = cp * s, bi = sp * s;      // e*s = (br, bi)
                float air = ur[i], aii = ui[i];
                float ajr = ur[j], aji = ui[j];
                // U[i] = c*ri - conj(e)*s*rj
                ur[i] = c * air - (br * ajr + bi * aji);
                ui[i] = c * aii - (br * aji - bi * ajr);
                // U[j] = e*s*ri + c*rj
                ur[j] = (br * air - bi * aii) + c * ajr;
                ui[j] = (br * aii + bi * air) + c * aji;
                ++k;
            }
        }
        // expand to real symplectic [[Re, -Im], [Im, Re]]
        #pragma unroll
        for (int m = 0; m < 16; ++m) {
            g_S[g][m][col]           =  ur[m];
            g_S[g][m][col + 16]      = -ui[m];
            g_S[g][m + 16][col]      =  ui[m];
            g_S[g][m + 16][col + 16] =  ur[m];
        }
    }

    if (tid < 192) {
        // ---- squeezing scales + displacement ----
        int l = tid >> 5, kk = tid & 31;
        const float* lp = lin + l * LIN_P;
        float r = lp[240 + (kk & 15)];
        s_scale[l][kk] = __expf(kk < 16 ? -r : r);
        g_d[l][kk] = lp[496 + kk];
    }
    __syncthreads();

    // ---- compose W[l][i][o] = sum_k S2[o][k]*scale[k]*S1[k][i] ----
    {
        int i = tid >> 5, o = tid & 31;
        #pragma unroll 1
        for (int l = 0; l < N_LAYERS; ++l) {
            float acc = 0.f;
            #pragma unroll
            for (int k = 0; k < 32; ++k)
                acc += g_S[2 * l + 1][o][k] * s_scale[l][k] * g_S[2 * l][k][i];
            g_W[l][i][o] = acc;
        }
    }
    __syncthreads();

    // ---- compact last layer: keep only outputs {0..9, 16..25} ----
    if (tid < 640) {
        int i = tid / 20, j = tid % 20;
        g_Wc[i][j] = g_W[N_LAYERS - 1][i][j < 10 ? j : j + 6];
    }
    if (tid < 20) g_dc[tid] = g_d[N_LAYERS - 1][tid < 10 ? tid : tid + 6];
}

// ---------------------------------------------------------------------------
// Affine layer on TWO samples: one LDS.128 of weights feeds 4 FFMA2s.
// W laid out [in][out], STRIDE floats per row; NP output f32x2 pairs.
// ---------------------------------------------------------------------------
template<int NIN, int NP, int STRIDE>
__device__ __forceinline__ void linear2(float* va, float* vb,
                                        const float* __restrict__ W,
                                        const float* __restrict__ dv) {
    ull a0[NP], a1[NP];
    #pragma unroll
    for (int k = 0; k < NP; ++k) {
        ull t = pack2(dv[2 * k], dv[2 * k + 1]);
        a0[k] = t; a1[k] = t;
    }
    #pragma unroll
    for (int i = 0; i < NIN; ++i) {
        ull da = dup_f32(va[i]);
        ull db = dup_f32(vb[i]);
        const ulonglong2* wr = reinterpret_cast<const ulonglong2*>(W + i * STRIDE);
        #pragma unroll
        for (int q = 0; q < NP / 2; ++q) {
            ulonglong2 w2 = wr[q];                 // 4 weights = 2 output pairs
            a0[2 * q]     = ffma2(da, w2.x, a0[2 * q]);
            a0[2 * q + 1] = ffma2(da, w2.y, a0[2 * q + 1]);
            a1[2 * q]     = ffma2(db, w2.x, a1[2 * q]);
            a1[2 * q + 1] = ffma2(db, w2.y, a1[2 * q + 1]);
        }
    }
    #pragma unroll
    for (int k = 0; k < NP; ++k) {
        unpack2(a0[k], va[2 * k], va[2 * k + 1]);
        unpack2(a1[k], vb[2 * k], vb[2 * k + 1]);
    }
}

__device__ __forceinline__ void kerr16(float* v, const float* __restrict__ kp) {
    #pragma unroll
    for (int m = 0; m < 16; ++m) {
        float x = v[m], p = v[m + 16];
        float ang = kp[m] * (x * x + p * p);
        float s, c;
        __sincosf(ang, &s, &c);
        v[m]      = fmaf(c, x,  s * p);
        v[m + 16] = fmaf(c, p, -s * x);
    }
}

// ---------------------------------------------------------------------------
// Main kernel: 2 samples per thread; state in registers; weights in SMEM.
// ---------------------------------------------------------------------------
__global__ void __launch_bounds__(TPB) qnet_main(
    const float* __restrict__ batch,
    const float* __restrict__ act_p,      // (5, 16)
    const float* __restrict__ last_act,   // (16,)
    float* __restrict__ out,
    int n_samples)
{
    __shared__ __align__(16) float sW[N_LAYERS - 1][32][32];  // layers 0..4: 20 KB
    __shared__ __align__(16) float sWc[32][20];               // layer 5 compact
    __shared__ float sd[N_LAYERS - 1][32];
    __shared__ float sdc[20];
    __shared__ float sk[N_LAYERS][16];

    int tid = threadIdx.x;
    {
        const float4* src = reinterpret_cast<const float4*>(g_W);
        float4* dst = reinterpret_cast<float4*>(&sW[0][0][0]);
        for (int idx = tid; idx < (N_LAYERS - 1) * 32 * 32 / 4; idx += TPB) dst[idx] = src[idx];
        const float4* srcc = reinterpret_cast<const float4*>(&g_Wc[0][0]);
        float4* dstc = reinterpret_cast<float4*>(&sWc[0][0]);
        for (int idx = tid; idx < 32 * 20 / 4; idx += TPB) dstc[idx] = srcc[idx];
        // strided loop: (N_LAYERS-1)*32 = 160 > TPB, a plain conditional here
        // silently leaves sd[4][...] uninitialized (the R2 bug)
        for (int idx = tid; idx < (N_LAYERS - 1) * 32; idx += TPB)
            (&sd[0][0])[idx] = (&g_d[0][0])[idx];
        if (tid < 20) sdc[tid] = g_dc[tid];
        if (tid < 80)       (&sk[0][0])[tid] = act_p[tid];
        else if (tid < 96)  (&sk[0][0])[tid] = last_act[tid - 80];
    }
    __syncthreads();

    int sa = blockIdx.x * (TPB * SPT) + tid;          // sample A
    int sb = sa + TPB;                                // sample B (coalesced)

    float va[32], vb[32];
    {
        const float4* ba = reinterpret_cast<const float4*>(batch + (size_t)sa * 16);
        const float4* bb = reinterpret_cast<const float4*>(batch + (size_t)sb * 16);
        #pragma unroll
        for (int q = 0; q < 4; ++q) {
            float4 t = (sa < n_samples) ? ba[q] : make_float4(0.f, 0.f, 0.f, 0.f);
            va[4 * q] = t.x; va[4 * q + 1] = t.y; va[4 * q + 2] = t.z; va[4 * q + 3] = t.w;
            float4 u = (sb < n_samples) ? bb[q] : make_float4(0.f, 0.f, 0.f, 0.f);
            vb[4 * q] = u.x; vb[4 * q + 1] = u.y; vb[4 * q + 2] = u.z; vb[4 * q + 3] = u.w;
        }
        #pragma unroll
        for (int m = 16; m < 32; ++m) { va[m] = 0.f; vb[m] = 0.f; }
    }

    // layer 0: inputs 16..31 are zero -> only 16 i-steps
    linear2<16, 16, 32>(va, vb, &sW[0][0][0], &sd[0][0]);
    kerr16(va, &sk[0][0]);
    kerr16(vb, &sk[0][0]);

    #pragma unroll 1
    for (int l = 1; l < N_LAYERS - 1; ++l) {
        linear2<32, 16, 32>(va, vb, &sW[l][0][0], &sd[l][0]);
        kerr16(va, &sk[l][0]);
        kerr16(vb, &sk[l][0]);
    }

    // last layer: only outputs x0..x9 (cols 0..9) and p0..p9 (cols 10..19)
    linear2<32, 10, 20>(va, vb, &sWc[0][0], sdc);

    float oa[OUT_COLS], ob[OUT_COLS];
    #pragma unroll
    for (int m = 0; m < OUT_COLS; ++m) {
        float ka = sk[N_LAYERS - 1][m];
        float x = va[m], p = va[10 + m];
        float ang = ka * (x * x + p * p);
        float s, c;
        __sincosf(ang, &s, &c);
        oa[m] = fmaf(c, x, s * p);
        x = vb[m]; p = vb[10 + m];
        ang = ka * (x * x + p * p);
        __sincosf(ang, &s, &c);
        ob[m] = fmaf(c, x, s * p);
    }

    if (sa < n_samples) {
        float2* orow = reinterpret_cast<float2*>(out + (size_t)sa * OUT_COLS);
        #pragma unroll
        for (int m = 0; m < 5; ++m) orow[m] = make_float2(oa[2 * m], oa[2 * m + 1]);
    }
    if (sb < n_samples) {
        float2* orow = reinterpret_cast<float2*>(out + (size_t)sb * OUT_COLS);
        #pragma unroll
        for (int m = 0; m < 5; ++m) orow[m] = make_float2(ob[2 * m], ob[2 * m + 1]);
    }
}

// ---------------------------------------------------------------------------
extern "C" void kernel_launch(void* const* d_in, const int* in_sizes, int n_in,
                              void* d_out, int out_size) {
    const float* batch    = (const float*)d_in[0];   // (B, 16)
    const float* lin      = (const float*)d_in[1];   // (6, 528)
    const float* act_p    = (const float*)d_in[2];   // (5, 16)
    const float* last_act = (const float*)d_in[3];   // (16,)
    float* out = (float*)d_out;

    int n_samples = in_sizes[0] / N_MODES;
    int blocks = (n_samples + TPB * SPT - 1) / (TPB * SPT);

    setup_kernel<<<1, 1024>>>(lin);
    qnet_main<<<blocks, TPB>>>(batch, act_p, last_act, out, n_samples);
}